// round 17
// baseline (speedup 1.0000x reference)
#include <cuda_runtime.h>
#include <cuda_fp16.h>
#include <cstdint>

// ---------------- problem dims ----------------
#define E_  100
#define B_  1024
#define D_  2048
#define H1_ 512
#define H2_ 256

// ---------------- scratch (__device__ globals; no cudaMalloc allowed) ----
__device__ __half g_xh [(size_t)B_ * D_];          //   4MB
__device__ __half g_w1h[(size_t)E_ * D_ * H1_];    // 210MB
__device__ __half g_w2h[(size_t)E_ * H1_ * H2_];   //  26MB
__device__ __half g_h1h[(size_t)E_ * B_ * H1_];    // 105MB

// ---------------- device helpers ----------------
__device__ __forceinline__ uint32_t smem_u32(const void* p) {
    uint32_t a;
    asm("{ .reg .u64 t; cvta.to.shared.u64 t, %1; cvt.u32.u64 %0, t; }" : "=r"(a) : "l"(p));
    return a;
}
__device__ __forceinline__ void cp_async16(uint32_t s, const void* g) {
    asm volatile("cp.async.cg.shared.global [%0], [%1], 16;" :: "r"(s), "l"(g));
}
__device__ __forceinline__ void cp_commit() {
    asm volatile("cp.async.commit_group;" ::: "memory");
}
__device__ __forceinline__ void ldsm4(uint32_t r[4], uint32_t addr) {
    asm volatile("ldmatrix.sync.aligned.m8n8.x4.shared.b16 {%0,%1,%2,%3}, [%4];"
        : "=r"(r[0]), "=r"(r[1]), "=r"(r[2]), "=r"(r[3]) : "r"(addr));
}
__device__ __forceinline__ void ldsm4t(uint32_t& r0, uint32_t& r1, uint32_t& r2, uint32_t& r3,
                                       uint32_t addr) {
    asm volatile("ldmatrix.sync.aligned.m8n8.x4.trans.shared.b16 {%0,%1,%2,%3}, [%4];"
        : "=r"(r0), "=r"(r1), "=r"(r2), "=r"(r3) : "r"(addr));
}
__device__ __forceinline__ void mma_f16(float c[4], const uint32_t a[4], const uint32_t b[2]) {
    asm volatile(
        "mma.sync.aligned.m16n8k16.row.col.f32.f16.f16.f32 "
        "{%0,%1,%2,%3}, {%4,%5,%6,%7}, {%8,%9}, {%0,%1,%2,%3};"
        : "+f"(c[0]), "+f"(c[1]), "+f"(c[2]), "+f"(c[3])
        : "r"(a[0]), "r"(a[1]), "r"(a[2]), "r"(a[3]), "r"(b[0]), "r"(b[1]));
}

// ---------------- shared geometry (R9/R13-proven tile) ----------------
#define MT 128
#define NT 128
#define KC 64
#define A_STRIDE 144                 // 64 fp16 = 128B data + 16B pad
#define B_STRIDE 272                 // 128 fp16 = 256B data + 16B pad
#define A_TILE_B (MT * A_STRIDE)     // 18432
#define B_TILE_B (KC * B_STRIDE)     // 17408
#define STAGE_B  (A_TILE_B + B_TILE_B)   // 35840
#define SMEM_TOT (3 * STAGE_B)           // 107520

// ---------------- persistent GEMM: tiles streamed through one CTA --------
// 128x128 tile, 4 warps (2m x 2n), warp tile 64x64, 2 CTAs/SM.
// The 3-stage cp.async ring runs CONTINUOUSLY across tile boundaries:
// prologue cost paid once per CTA instead of once per tile; epilogue
// overlaps the next tile's in-flight loads.
// FUSEL3: epilogue = relu(acc+bias).w3 partial dot -> atomicAdd into outF
//         (outF pre-initialized to b3 by the l1 kernel's epilogue).
// !FUSEL3: epilogue = bias+relu -> fp16 C store; nt==0 also inits outF=b3.
template <bool FUSEL3>
__global__ void __launch_bounds__(128, 2)
gemm_pers(const __half* __restrict__ A, const __half* __restrict__ Bw,
          const float* __restrict__ bias, __half* __restrict__ C,
          const float* __restrict__ w3, const float* __restrict__ b3,
          float* __restrict__ outF,
          int nch, int ArowsPerE, int Ntot, unsigned long long strideCe,
          int nt_count, int ntiles) {
    extern __shared__ __align__(128) char smem[];
    const uint32_t sbase = smem_u32(smem);
    const int tid = threadIdx.x, lane = tid & 31, warp = tid >> 5;
    const int wm = warp >> 1, wn = warp & 1;
    const int G = gridDim.x;
    const int K = nch * KC;
    const int ldaB = K * 2, ldbB = Ntot * 2;

    const int my_tiles = (ntiles - blockIdx.x + G - 1) / G;
    if (my_tiles <= 0) return;
    const int total = my_tiles * nch;

    // ---- loader-side tile state ----
    int tile_l = blockIdx.x;
    int chunk_l = 0;
    const char *AbL = nullptr, *BbL = nullptr;
    auto set_load = [&](int t) {
        int nt = t % nt_count; int r = t / nt_count;
        int mt = r & 7; int e = r >> 3;
        AbL = (const char*)(A + ((size_t)e * ArowsPerE + (size_t)mt * MT) * K);
        BbL = (const char*)(Bw + (size_t)e * (size_t)K * Ntot + nt * NT);
    };
    set_load(tile_l);

    auto load_next = [&](int s) {
        const uint32_t st = sbase + s * STAGE_B;
        const char* Ac = AbL + chunk_l * KC * 2;
        #pragma unroll
        for (int it = 0; it < 8; it++) {
            int q = tid + it * 128;              // 128 rows x 8 segs
            int r = q >> 3, seg = (q & 7) * 16;
            cp_async16(st + r * A_STRIDE + seg, Ac + (size_t)r * ldaB + seg);
        }
        const char* Bc = BbL + (size_t)(chunk_l * KC) * ldbB;
        const uint32_t stb = st + A_TILE_B;
        #pragma unroll
        for (int it = 0; it < 8; it++) {
            int q = tid + it * 128;              // 64 rows x 16 segs
            int r = q >> 4, seg = (q & 15) * 16;
            cp_async16(stb + r * B_STRIDE + seg, Bc + (size_t)r * ldbB + seg);
        }
        cp_commit();
        if (++chunk_l == nch) {
            chunk_l = 0;
            tile_l += G;
            if (tile_l < ntiles) set_load(tile_l);
        }
    };

    // per-lane ldmatrix offsets (bytes)
    const uint32_t offA = (uint32_t)(lane & 15) * A_STRIDE + (uint32_t)(lane >> 4) * 16;
    const uint32_t offB = (uint32_t)(lane & 15) * B_STRIDE + (uint32_t)(lane >> 4) * 16;
    const uint32_t awoff = (uint32_t)wm * 64 * A_STRIDE + offA;
    const uint32_t bwoff = (uint32_t)wn * 128 + offB;         // wn*64 cols * 2B

    // double-buffered fragments
    uint32_t afr[2][4][4], bfr[2][8][2];
    auto prefetch = [&](uint32_t st, int ks, int buf) {
        const uint32_t sa = st + awoff + (uint32_t)ks * 32;
        #pragma unroll
        for (int i = 0; i < 4; i++)
            ldsm4(afr[buf][i], sa + (uint32_t)i * (16 * A_STRIDE));
        const uint32_t sb = st + A_TILE_B + bwoff + (uint32_t)ks * (16 * B_STRIDE);
        #pragma unroll
        for (int j2 = 0; j2 < 4; j2++) {
            uint32_t r0, r1, r2, r3;
            ldsm4t(r0, r1, r2, r3, sb + (uint32_t)j2 * 32);
            bfr[buf][j2 * 2][0] = r0;     bfr[buf][j2 * 2][1] = r1;
            bfr[buf][j2 * 2 + 1][0] = r2; bfr[buf][j2 * 2 + 1][1] = r3;
        }
    };

    float acc[4][8][4];
    #pragma unroll
    for (int i = 0; i < 4; i++)
        #pragma unroll
        for (int j = 0; j < 8; j++)
            #pragma unroll
            for (int r = 0; r < 4; r++) acc[i][j][r] = 0.0f;

    // ---- prologue: first two chunks in flight ----
    load_next(0);
    load_next(1);
    asm volatile("cp.async.wait_group 1;" ::: "memory");
    __syncthreads();
    prefetch(sbase, 0, 0);

    // ---- flat chunk-stream mainloop ----
    int tile_c = blockIdx.x;
    int stage_c = 0;      // stage of the chunk being computed
    int stage_n = 2;      // stage the next load targets
    int chunk_c = 0;

    for (int q = 0; q < total; q++) {
        const uint32_t st = sbase + stage_c * STAGE_B;
        if (q + 2 < total) { load_next(stage_n); if (++stage_n == 3) stage_n = 0; }

        #pragma unroll
        for (int ks = 0; ks < 4; ks++) {
            const int cur = ks & 1;
            if (ks < 3) prefetch(st, ks + 1, cur ^ 1);
            #pragma unroll
            for (int i = 0; i < 4; i++)
                #pragma unroll
                for (int j = 0; j < 8; j++)
                    mma_f16(acc[i][j], afr[cur][i], bfr[cur][j]);
        }

        if (++chunk_c == nch) {
            chunk_c = 0;
            // ---- per-tile epilogue (per-warp independent; overlaps loads) --
            const int ntl = tile_c % nt_count;
            const int rt = tile_c / nt_count;
            const int mtl = rt & 7, el = rt >> 3;
            const int n0 = ntl * NT;
            const int col0 = wn * 64 + (lane & 3) * 2;

            if (FUSEL3) {
                const float* bp = bias + (size_t)el * Ntot + n0;
                const float* wp = w3 + (size_t)el * H2_ + n0;
                #pragma unroll
                for (int i = 0; i < 4; i++) {
                    #pragma unroll
                    for (int rr = 0; rr < 2; rr++) {
                        float p = 0.0f;
                        #pragma unroll
                        for (int j = 0; j < 8; j++) {
                            const int col = col0 + j * 8;
                            float v0 = fmaxf(acc[i][j][rr * 2 + 0] + __ldg(bp + col), 0.0f);
                            float v1 = fmaxf(acc[i][j][rr * 2 + 1] + __ldg(bp + col + 1), 0.0f);
                            p += v0 * __ldg(wp + col) + v1 * __ldg(wp + col + 1);
                        }
                        p += __shfl_xor_sync(0xFFFFFFFFu, p, 1);
                        p += __shfl_xor_sync(0xFFFFFFFFu, p, 2);
                        if ((lane & 3) == 0) {
                            const int b = mtl * MT + wm * 64 + i * 16 + rr * 8 + (lane >> 2);
                            atomicAdd(&outF[(size_t)b * E_ + el], p);
                        }
                    }
                }
            } else {
                if (ntl == 0) outF[(size_t)(mtl * MT + tid) * E_ + el] = __ldg(b3 + el);
                const float* bp = bias + (size_t)el * Ntot + n0;
                const int mrow0 = mtl * MT + wm * 64 + (lane >> 2);
                __half* Ce = C + (size_t)el * strideCe + n0;
                #pragma unroll
                for (int i = 0; i < 4; i++) {
                    const size_t r0 = (size_t)(mrow0 + i * 16);
                    #pragma unroll
                    for (int j = 0; j < 8; j++) {
                        const int col = col0 + j * 8;
                        const float bx = __ldg(bp + col), by = __ldg(bp + col + 1);
                        float v0 = fmaxf(acc[i][j][0] + bx, 0.0f);
                        float v1 = fmaxf(acc[i][j][1] + by, 0.0f);
                        float v2 = fmaxf(acc[i][j][2] + bx, 0.0f);
                        float v3 = fmaxf(acc[i][j][3] + by, 0.0f);
                        *reinterpret_cast<__half2*>(Ce + r0 * Ntot + col)       = __floats2half2_rn(v0, v1);
                        *reinterpret_cast<__half2*>(Ce + (r0 + 8) * Ntot + col) = __floats2half2_rn(v2, v3);
                    }
                }
            }
            tile_c += G;
            #pragma unroll
            for (int i = 0; i < 4; i++)
                #pragma unroll
                for (int j = 0; j < 8; j++)
                    #pragma unroll
                    for (int r = 0; r < 4; r++) acc[i][j][r] = 0.0f;
        }

        if (q + 1 < total) {
            if (q + 2 < total) { asm volatile("cp.async.wait_group 1;" ::: "memory"); }
            else               { asm volatile("cp.async.wait_group 0;" ::: "memory"); }
            __syncthreads();
            int sn = stage_c + 1; if (sn == 3) sn = 0;
            prefetch(sbase + sn * STAGE_B, 0, 0);
            stage_c = sn;
        }
    }
}

// ---------------- single mega convert: W1 + x + W2 in ONE launch ----------
#define N4_W1 ((long)E_ * D_ * H1_ / 4)
#define N4_X  ((long)B_ * D_ / 4)
#define N4_W2 ((long)E_ * H1_ * H2_ / 4)

__global__ void convert_all(const float4* __restrict__ w1, uint2* __restrict__ w1h,
                            const float4* __restrict__ x,  uint2* __restrict__ xh,
                            const float4* __restrict__ w2, uint2* __restrict__ w2h) {
    long i = blockIdx.x * (long)blockDim.x + threadIdx.x;
    const float4* in; uint2* out; long k;
    if (i < N4_W1)                     { in = w1; out = w1h; k = i; }
    else if (i < N4_W1 + N4_X)         { in = x;  out = xh;  k = i - N4_W1; }
    else if (i < N4_W1 + N4_X + N4_W2) { in = w2; out = w2h; k = i - N4_W1 - N4_X; }
    else return;
    float4 v = in[k];
    __half2 lo = __floats2half2_rn(v.x, v.y);
    __half2 hi = __floats2half2_rn(v.z, v.w);
    uint2 o;
    o.x = *reinterpret_cast<uint32_t*>(&lo);
    o.y = *reinterpret_cast<uint32_t*>(&hi);
    out[k] = o;
}

// ---------------- host ----------------
extern "C" void kernel_launch(void* const* d_in, const int* in_sizes, int n_in,
                              void* d_out, int out_size) {
    const float* x  = (const float*)d_in[0];
    const float* W1 = (const float*)d_in[1];
    const float* b1 = (const float*)d_in[2];
    const float* W2 = (const float*)d_in[3];
    const float* b2 = (const float*)d_in[4];
    const float* W3 = (const float*)d_in[5];
    const float* b3 = (const float*)d_in[6];
    float* out = (float*)d_out;

    __half *xh, *w1h, *w2h, *h1h;
    cudaGetSymbolAddress((void**)&xh,  g_xh);
    cudaGetSymbolAddress((void**)&w1h, g_w1h);
    cudaGetSymbolAddress((void**)&w2h, g_w2h);
    cudaGetSymbolAddress((void**)&h1h, g_h1h);

    cudaFuncSetAttribute(gemm_pers<false>, cudaFuncAttributeMaxDynamicSharedMemorySize, SMEM_TOT);
    cudaFuncSetAttribute(gemm_pers<true>,  cudaFuncAttributeMaxDynamicSharedMemorySize, SMEM_TOT);

    int nsm = 148;
    {
        cudaDeviceProp prop;
        if (cudaGetDeviceProperties(&prop, 0) == cudaSuccess) nsm = prop.multiProcessorCount;
    }
    const int G = nsm * 2;   // 2 CTAs/SM, persistent

    // 1) one convert launch for W1 + x + W2
    {
        long tot = N4_W1 + N4_X + N4_W2;
        convert_all<<<(unsigned)((tot + 255) / 256), 256>>>(
            (const float4*)W1, (uint2*)w1h,
            (const float4*)x,  (uint2*)xh,
            (const float4*)W2, (uint2*)w2h);
    }

    // 2) layer 1 (persistent): tiles = 4 nt x 8 mt x 100 e = 3200;
    //    relu(x W1 + b1) -> h1 fp16; nt==0 tiles also init out = b3
    {
        int ntiles = 3200;
        int grid = G < ntiles ? G : ntiles;
        gemm_pers<false><<<grid, 128, SMEM_TOT>>>(
            xh, w1h, b1, h1h, nullptr, b3, out,
            D_ / KC, /*ArowsPerE=*/0, /*Ntot=*/H1_,
            (unsigned long long)B_ * H1_,
            /*nt_count=*/4, ntiles);
    }

    // 3) layer 2 + fused layer 3 (persistent): tiles = 2 x 8 x 100 = 1600;
    //    relu(h1 W2 + b2) . W3 accumulated atomically into out
    {
        int ntiles = 1600;
        int grid = G < ntiles ? G : ntiles;
        gemm_pers<true><<<grid, 128, SMEM_TOT>>>(
            h1h, w2h, b2, nullptr, W3, b3, out,
            H1_ / KC, /*ArowsPerE=*/B_, /*Ntot=*/H2_,
            0ULL,
            /*nt_count=*/2, ntiles);
    }
}